// round 17
// baseline (speedup 1.0000x reference)
#include <cuda_runtime.h>
#include <cuda_bf16.h>

#define T_LEN   32768
#define C_LEN   512
#define B_LEN   8
#define KSZ     12
#define NT      256
#define NW      8
#define WTILE   512               // outputs per warp
#define BTILE   4096              // outputs per block
#define NBLK    (T_LEN / BTILE)   // 8
#define TOFS    8                 // left halo floats in tile
#define TILE_F  (TOFS + BTILE + 12)   // 4116 floats = 16464 B
#define EPS_F   1e-9f

__device__ __forceinline__ float snake(float v, float a, float binv) {
    float sn = __sinf(v * a);
    return fmaf(sn * sn, binv, v);
}

// One output quad: outputs j0..j0+3, j0 = w0 + Q*128 + S + l*4 (16B-aligned store).
// Window needed: tile frame [j0-6-w0 .. j0+9-w0]; read 5 aligned float4s covering it.
template<int S, int Q>
__device__ __forceinline__ void quad_out(const float* __restrict__ tw,   // tile + TOFS + wp*512
                                         const float (&f)[KSZ],
                                         float* __restrict__ orow, int w0, int l, bool trim) {
    constexpr int A0  = (S - 6) & ~3;       // aligned window start (-8 or -4)
    constexpr int off = (S - 6) - A0;       // 2,3,0,1 for S=0,1,2,3
    const float* tp = tw + Q * 128 + A0 + l * 4;

    float r[20];
    #pragma unroll
    for (int i = 0; i < 5; ++i) {
        float4 q = *(const float4*)(tp + i * 4);
        r[i * 4 + 0] = q.x; r[i * 4 + 1] = q.y;
        r[i * 4 + 2] = q.z; r[i * 4 + 3] = q.w;
    }

    float s0 = r[off + 0] * f[0], s1 = r[off + 1] * f[0];
    float s2 = r[off + 2] * f[0], s3 = r[off + 3] * f[0];
    #pragma unroll
    for (int k = 1; k < KSZ; ++k) {
        s0 = fmaf(r[off + 0 + k], f[k], s0);
        s1 = fmaf(r[off + 1 + k], f[k], s1);
        s2 = fmaf(r[off + 2 + k], f[k], s2);
        s3 = fmaf(r[off + 3 + k], f[k], s3);
    }

    const int j0 = w0 + Q * 128 + S + l * 4;
    if constexpr (S >= 2 && Q == 3) {
        if (trim) {   // last lane of last warp of last block: suppress j > T_LEN
            if (j0 + 0 <= T_LEN) orow[j0 + 0] = s0;
            if (j0 + 1 <= T_LEN) orow[j0 + 1] = s1;
            if (j0 + 2 <= T_LEN) orow[j0 + 2] = s2;
            if (j0 + 3 <= T_LEN) orow[j0 + 3] = s3;
            return;
        }
    }
    __stcs((float4*)(orow + j0), make_float4(s0, s1, s2, s3));
}

template<int S>
__device__ __forceinline__ void run_all(const float* __restrict__ tw, const float (&f)[KSZ],
                                        float* __restrict__ orow, int w0, int l, bool trim) {
    quad_out<S, 0>(tw, f, orow, w0, l, trim);
    quad_out<S, 1>(tw, f, orow, w0, l, trim);
    quad_out<S, 2>(tw, f, orow, w0, l, trim);
    quad_out<S, 3>(tw, f, orow, w0, l, trim);
}

// Front outputs [0, S) of a row, scalar with reflect.
template<int S>
__device__ __forceinline__ void front_fix(const float* __restrict__ xr, const float (&f)[KSZ],
                                          float* __restrict__ orow, float a, float binv) {
    #pragma unroll
    for (int j = 0; j < S; ++j) {
        float acc = 0.0f;
        #pragma unroll
        for (int k = 0; k < KSZ; ++k) {
            int g = j - 6 + k;
            if (g < 0) g = -g;
            acc = fmaf(snake(xr[g], a, binv), f[k], acc);
        }
        orow[j] = acc;
    }
}

__global__ __launch_bounds__(NT, 6)   // 40-reg cap, 48 warps/SM
void snake_aa_kernel(const float* __restrict__ x,
                     const float* __restrict__ alpha,
                     const float* __restrict__ beta,
                     const float* __restrict__ filt,
                     float* __restrict__ out) {
    __shared__ float tile[TILE_F];    // snaked inputs, frame [-8, BTILE+12)

    const int row = blockIdx.y;       // b*C + c
    const int c   = row & (C_LEN - 1);
    const int t0  = blockIdx.x * BTILE;
    const int tid = threadIdx.x;
    const int wp  = tid >> 5;
    const int l   = tid & 31;

    const float a    = __expf(alpha[c]);
    const float binv = 1.0f / (__expf(beta[c]) + EPS_F);
    const float* __restrict__ xr = x + (size_t)row * T_LEN;

    const int w0 = t0 + wp * WTILE;

    // Coalesced bulk loads: warp covers frame [wp*512, wp*512+512).
    const float4* __restrict__ xv = (const float4*)(xr + w0);
    float4 q0 = __ldcs(&xv[l]);
    float4 q1 = __ldcs(&xv[32 + l]);
    float4 q2 = __ldcs(&xv[64 + l]);
    float4 q3 = __ldcs(&xv[96 + l]);

    // Halo: 8 left + 12 right, loaded by 20 threads with reflect.
    if (tid < 20) {
        int g, ti;
        if (tid < 8) {
            g  = t0 - 8 + tid;
            ti = tid;                          // tile[TOFS + (-8+tid)]
            if (g < 0) g = -g;
        } else {
            g  = t0 + BTILE + (tid - 8);
            ti = TOFS + BTILE + (tid - 8);
            if (g >= T_LEN) g = 2 * (T_LEN - 1) - g;
        }
        tile[ti] = snake(xr[g], a, binv);
    }

    // Snake + STS.128 into tile (conflict-free: lane stride 16B).
    float* tw = tile + TOFS + wp * WTILE;
    *(float4*)(tw + 0 * 128 + l * 4) = make_float4(
        snake(q0.x, a, binv), snake(q0.y, a, binv), snake(q0.z, a, binv), snake(q0.w, a, binv));
    *(float4*)(tw + 1 * 128 + l * 4) = make_float4(
        snake(q1.x, a, binv), snake(q1.y, a, binv), snake(q1.z, a, binv), snake(q1.w, a, binv));
    *(float4*)(tw + 2 * 128 + l * 4) = make_float4(
        snake(q2.x, a, binv), snake(q2.y, a, binv), snake(q2.z, a, binv), snake(q2.w, a, binv));
    *(float4*)(tw + 3 * 128 + l * 4) = make_float4(
        snake(q3.x, a, binv), snake(q3.y, a, binv), snake(q3.z, a, binv), snake(q3.w, a, binv));

    __syncthreads();

    // Filter: 3 uniform float4 loads.
    float f[KSZ];
    {
        const float4* fv = (const float4*)filt;
        float4 f0 = __ldg(&fv[0]), f1 = __ldg(&fv[1]), f2 = __ldg(&fv[2]);
        f[0]=f0.x; f[1]=f0.y; f[2]=f0.z;  f[3]=f0.w;
        f[4]=f1.x; f[5]=f1.y; f[6]=f1.z;  f[7]=f1.w;
        f[8]=f2.x; f[9]=f2.y; f[10]=f2.z; f[11]=f2.w;
    }

    float* __restrict__ orow = out + (size_t)row * (T_LEN + 1);
    const int  s    = (4 - (row & 3)) & 3;    // (-row) mod 4 — store alignment shift
    const bool last = (blockIdx.x == NBLK - 1);
    const bool trim = last && (wp == NW - 1) && (l == 31);

    switch (s) {
    case 0:
        run_all<0>(tw, f, orow, w0, l, trim);
        if (last && tid == 0) {   // tail output t = T_LEN
            float accv = 0.0f;
            #pragma unroll
            for (int k = 0; k < KSZ; ++k) {
                int g = T_LEN - 6 + k;
                if (g >= T_LEN) g = 2 * (T_LEN - 1) - g;
                accv = fmaf(snake(xr[g], a, binv), f[k], accv);
            }
            orow[T_LEN] = accv;
        }
        break;
    case 1:
        run_all<1>(tw, f, orow, w0, l, trim);
        if (blockIdx.x == 0 && tid == 0) front_fix<1>(xr, f, orow, a, binv);
        break;
    case 2:
        run_all<2>(tw, f, orow, w0, l, trim);
        if (blockIdx.x == 0 && tid == 0) front_fix<2>(xr, f, orow, a, binv);
        break;
    default:
        run_all<3>(tw, f, orow, w0, l, trim);
        if (blockIdx.x == 0 && tid == 0) front_fix<3>(xr, f, orow, a, binv);
        break;
    }
}

extern "C" void kernel_launch(void* const* d_in, const int* in_sizes, int n_in,
                              void* d_out, int out_size) {
    const float* x     = (const float*)d_in[0];
    const float* alpha = (const float*)d_in[1];
    const float* beta  = (const float*)d_in[2];
    const float* filt  = (const float*)d_in[3];
    float* out = (float*)d_out;

    dim3 grid(NBLK, B_LEN * C_LEN);   // (8, 4096)
    snake_aa_kernel<<<grid, NT>>>(x, alpha, beta, filt, out);
}